// round 13
// baseline (speedup 1.0000x reference)
#include <cuda_runtime.h>
#include <cuda_bf16.h>
#include <math.h>
#include <stdint.h>

#define NG 1024
#define HD 128
#define ET 500000
#define NN 100000
#define SQRT_H 11.313708498984761f

#define TM 64                  // edges per CTA
#define KP 392                 // padded A row pitch (bf16 elems)
#define NKS 24                 // K16 steps
#define EDGE_BLKS ((ET + TM - 1) / TM)   // 7813

// ---------------- scratch (device globals; no allocation allowed) ----------------
__device__ float    g_tsum[NN];
__device__ float    g_logits[ET];
__device__ float    g_logpb[NG];
__device__ int      g_selcnt[NG];
__device__ int      g_mflag;
__device__ float    g_U[HD];    // sum_k bf16(g_k*W[k,n])
__device__ float    g_Vb[HD];   // sum_k b_k*W[k,n] + bb1[n]  (f32 exact)
// W1 HMMA B-fragments with LN-gamma folded, quad-packed
__device__ __align__(16) unsigned g_Bf0[NKS * 16 * 32];
__device__ __align__(16) unsigned g_Bf1[NKS * 16 * 32];

// ---------------- helpers ----------------
__device__ __forceinline__ float gelu_f(float x){
    return 0.5f * x * (1.0f + erff(x * 0.70710678118654752440f));
}
__device__ __forceinline__ float gelu_t(float x){
    float u = fmaf(0.044715f * x * x, x, x) * 0.7978845608028654f;
    float th;
    asm("tanh.approx.f32 %0, %1;" : "=f"(th) : "f"(u));
    return 0.5f * x * (1.0f + th);
}
__device__ __forceinline__ float4 ld4(const float* p){ return *(const float4*)p; }

__device__ __forceinline__ uint32_t smem_u32(const void* p){
    uint32_t a;
    asm("{ .reg .u64 t; cvta.to.shared.u64 t, %1; cvt.u32.u64 %0, t; }" : "=r"(a) : "l"(p));
    return a;
}
__device__ __forceinline__ unsigned packbf2(float lo, float hi){
    __nv_bfloat162 v;
    v.x = __float2bfloat16(lo);
    v.y = __float2bfloat16(hi);
    return *(unsigned*)&v;
}
__device__ __forceinline__ float rbf(float x){   // round through bf16
    return __bfloat162float(__float2bfloat16(x));
}
__device__ __forceinline__ void ldm_x4(uint32_t* r, uint32_t addr){
    asm volatile("ldmatrix.sync.aligned.m8n8.x4.shared.b16 {%0,%1,%2,%3}, [%4];"
                 : "=r"(r[0]), "=r"(r[1]), "=r"(r[2]), "=r"(r[3]) : "r"(addr));
}
__device__ __forceinline__ void mma16816(float* d, const uint32_t* a,
                                         uint32_t b0, uint32_t b1){
    asm volatile(
        "mma.sync.aligned.m16n8k16.row.col.f32.bf16.bf16.f32 "
        "{%0,%1,%2,%3}, {%4,%5,%6,%7}, {%8,%9}, {%0,%1,%2,%3};"
        : "+f"(d[0]), "+f"(d[1]), "+f"(d[2]), "+f"(d[3])
        : "r"(a[0]), "r"(a[1]), "r"(a[2]), "r"(a[3]), "r"(b0), "r"(b1));
}

__device__ __forceinline__ float bsum256(float v, float* red){
    #pragma unroll
    for (int o = 16; o > 0; o >>= 1) v += __shfl_xor_sync(0xFFFFFFFFu, v, o);
    int w = threadIdx.x >> 5;
    if ((threadIdx.x & 31) == 0) red[w] = v;
    __syncthreads();
    if (threadIdx.x == 0){
        float s = red[0];
        #pragma unroll
        for (int i = 1; i < 8; i++) s += red[i];
        red[0] = s;
    }
    __syncthreads();
    float r = red[0];
    __syncthreads();
    return r;
}

// ---------------- prep ----------------
__global__ void k_prep(const unsigned* __restrict__ mask, const float* __restrict__ bw1,
                       const float* __restrict__ blng, const float* __restrict__ blnb,
                       const float* __restrict__ bb1){
    int i = blockIdx.x * blockDim.x + threadIdx.x;
    if (i < NN) g_tsum[i] = 0.0f;
    if (i < NG){ g_logpb[i] = 0.0f; g_selcnt[i] = 0; }
    if (i < 4096){
        unsigned w = mask[i];
        int f = (w == 0x3F800000u) ? 1 : ((w > 1u) ? 2 : 0);
        if (f) atomicOr(&g_mflag, f);
    }
    if (i < NKS * 512){
        int lane = i & 31, nt = (i >> 5) & 15, s = i >> 9;
        int n  = nt * 8 + (lane >> 2);
        int k0 = s * 16 + (lane & 3) * 2;
        int o  = s * 512 + (nt >> 2) * 128 + lane * 4 + (nt & 3);
        g_Bf0[o] = packbf2(blng[k0]     * bw1[k0 * HD + n],
                           blng[k0 + 1] * bw1[(k0 + 1) * HD + n]);
        g_Bf1[o] = packbf2(blng[k0 + 8] * bw1[(k0 + 8) * HD + n],
                           blng[k0 + 9] * bw1[(k0 + 9) * HD + n]);
    }
    // U / Vb (block 0, threads < HD)
    if (blockIdx.x == 0 && threadIdx.x < HD){
        int n = threadIdx.x;
        float u = 0.f, vb = 0.f;
        for (int k = 0; k < 384; k++){
            float wv = bw1[k * HD + n];
            u  += rbf(blng[k] * wv);
            vb  = fmaf(blnb[k], wv, vb);
        }
        g_U[n]  = u;
        g_Vb[n] = vb + bb1[n];
    }
}

// ---------------- fused main kernel: graph blocks [0,NG) + edge blocks ----------------
// dyn smem (edge): A[64][392] bf16 (50176) | tgt 256 | mean 256 | rstd 256 | part 512
#define OFF_A    0
#define OFF_TGT  50176
#define OFF_MEAN 50432
#define OFF_RSTD 50688
#define OFF_PART 50944
#define MAIN_SMEM 51456

__global__ __launch_bounds__(256, 3) void k_main(
    const float* __restrict__ node, const float* __restrict__ ques,
    const float* __restrict__ etok,
    const float* __restrict__ bw2,  const float* __restrict__ bb2,
    const int* __restrict__ ebatch, const int* __restrict__ eidx,
    const float* __restrict__ ln1g, const float* __restrict__ ln1b,
    const float* __restrict__ zw1,  const float* __restrict__ zb1,
    const float* __restrict__ zw2,  const float* __restrict__ zb2,
    const float* __restrict__ cw1,  const float* __restrict__ cb1,
    const float* __restrict__ cw2,  const float* __restrict__ cb2,
    const int* __restrict__ locals, const int* __restrict__ ptr,
    float* __restrict__ out)
{
    extern __shared__ char sm[];
    int t = threadIdx.x, lane = t & 31, w = t >> 5;

    if (blockIdx.x < NG){
        // ================= graph path (unchanged) =================
        float* xs  = (float*)sm;
        float* hs  = xs + 256;
        float* red = hs + 128;
        float* sc  = red + 8;
        int*  locs = (int*)(sc + 32);

        int g = blockIdx.x;
        bool act = t < 128;
        float q = act ? ques[g * HD + t] : 0.0f;
        if (act) xs[HD + t] = q;

        int p0 = ptr[g], p1 = ptr[g + 1];
        int cnt = p1 - p0; if (cnt > 32) cnt = 32;

        float4 qv = ld4(ques + (size_t)g * HD + lane * 4);
        for (int i = w; i < cnt; i += 8){
            int loc = locals[p0 + i];
            float4 nv = ld4(node + (size_t)loc * HD + lane * 4);
            float d = nv.x*qv.x + nv.y*qv.y + nv.z*qv.z + nv.w*qv.w;
            #pragma unroll
            for (int o = 16; o > 0; o >>= 1) d += __shfl_xor_sync(0xFFFFFFFFu, d, o);
            if (lane == 0){ sc[i] = d / SQRT_H; locs[i] = loc; }
        }
        __syncthreads();

        if (act){
            float m = -1e30f;
            for (int i = 0; i < cnt; i++) m = fmaxf(m, sc[i]);
            float den = 0.0f;
            for (int i = 0; i < cnt; i++) den += expf(sc[i] - m);
            float summ = 0.0f;
            for (int i = 0; i < cnt; i++){
                float a = expf(sc[i] - m) / den;
                summ += a * node[(size_t)locs[i] * HD + t];
            }
            xs[t] = summ;
        }
        __syncthreads();

        float ctx = 0.0f;
        if (act){
            float a0 = 0.f, a1 = 0.f, a2 = 0.f, a3 = 0.f;
            #pragma unroll 4
            for (int k = 0; k < 2 * HD; k += 4){
                a0 = fmaf(xs[k],     cw1[k * HD + t],       a0);
                a1 = fmaf(xs[k + 1], cw1[(k + 1) * HD + t], a1);
                a2 = fmaf(xs[k + 2], cw1[(k + 2) * HD + t], a2);
                a3 = fmaf(xs[k + 3], cw1[(k + 3) * HD + t], a3);
            }
            hs[t] = gelu_f(cb1[t] + ((a0 + a1) + (a2 + a3)));
        }
        __syncthreads();
        if (act){
            float a0 = 0.f, a1 = 0.f, a2 = 0.f, a3 = 0.f;
            #pragma unroll 4
            for (int k = 0; k < HD; k += 4){
                a0 = fmaf(hs[k],     cw2[k * HD + t],       a0);
                a1 = fmaf(hs[k + 1], cw2[(k + 1) * HD + t], a1);
                a2 = fmaf(hs[k + 2], cw2[(k + 2) * HD + t], a2);
                a3 = fmaf(hs[k + 3], cw2[(k + 3) * HD + t], a3);
            }
            ctx = cb2[t] + ((a0 + a1) + (a2 + a3));
        }

        float mean = bsum256(act ? ctx : 0.0f, red) * (1.0f / HD);
        float msq  = bsum256(act ? ctx * ctx : 0.0f, red) * (1.0f / HD);
        float rstd = rsqrtf(msq - mean * mean + 1e-5f);
        if (act) xs[t] = (ctx - mean) * rstd * ln1g[t] + ln1b[t];
        __syncthreads();

        float hz = 0.0f;
        if (act){
            float a0 = 0.f, a1 = 0.f, a2 = 0.f, a3 = 0.f;
            #pragma unroll 4
            for (int k = 0; k < HD; k += 4){
                a0 = fmaf(xs[k],     zw1[k * HD + t],       a0);
                a1 = fmaf(xs[k + 1], zw1[(k + 1) * HD + t], a1);
                a2 = fmaf(xs[k + 2], zw1[(k + 2) * HD + t], a2);
                a3 = fmaf(xs[k + 3], zw1[(k + 3) * HD + t], a3);
            }
            hz = gelu_f(zb1[t] + ((a0 + a1) + (a2 + a3))) * zw2[t];
        }
        float lz = bsum256(act ? hz : 0.0f, red);
        if (t == 0) out[g * 3 + 0] = lz + zb2[0];
        return;
    }

    // ================= edge path: raw-A gather (LN folded into epilogue) =================
    __nv_bfloat16* As = (__nv_bfloat16*)(sm + OFF_A);
    int*   tgt_s  = (int*)(sm + OFF_TGT);
    float* sMean  = (float*)(sm + OFF_MEAN);
    float* sRstd  = (float*)(sm + OFF_RSTD);
    float* part   = (float*)(sm + OFF_PART);   // [2][64]

    int gid = lane >> 2, tig = lane & 3;
    int e0 = (blockIdx.x - NG) * TM;

    // warp w gathers rows [rbase, rbase+8); pair {w&3, (w&3)+4} covers 16 rows
    int rbase = (w & 3) * 16 + (w >> 2) * 8;

    // ---- lane-parallel index prefetch: lanes 0-7 ebatch, 16-23 eidx[1] ----
    int myidx = 0;
    {
        int ei = e0 + rbase + (lane & 7);
        if (ei < ET && (lane < 8 || (lane >= 16 && lane < 24)))
            myidx = (lane < 8) ? ebatch[ei] : eidx[ET + ei];
        if (lane >= 16 && lane < 24)
            tgt_s[rbase + (lane - 16)] = (ei < ET) ? myidx : 0;
    }

    // ---- A: gather raw rows -> bf16; sums feed epilogue LN fold ----
    #pragma unroll 4
    for (int i = 0; i < 8; i++){
        int el = rbase + i;
        int e  = e0 + el;
        int k  = lane * 4;
        __nv_bfloat16* xr = As + el * KP;
        if (e >= ET){
            *(unsigned*)(xr + k) = 0;       *(unsigned*)(xr + k + 2) = 0;
            *(unsigned*)(xr + 128 + k) = 0; *(unsigned*)(xr + 128 + k + 2) = 0;
            *(unsigned*)(xr + 256 + k) = 0; *(unsigned*)(xr + 256 + k + 2) = 0;
            if (lane == 0){ sMean[el] = 0.f; sRstd[el] = 0.f; }
            continue;
        }
        int eb = __shfl_sync(0xFFFFFFFFu, myidx, i);
        int tg = __shfl_sync(0xFFFFFFFFu, myidx, 16 + i);
        float4 a = ld4(etok + (size_t)e  * HD + k);
        float4 b = ld4(ques + (size_t)eb * HD + k);
        float4 c = ld4(node + (size_t)tg * HD + k);
        // pack immediately (no LN dependency)
        *(unsigned*)(xr + k)           = packbf2(a.x, a.y);
        *(unsigned*)(xr + k + 2)       = packbf2(a.z, a.w);
        *(unsigned*)(xr + 128 + k)     = packbf2(b.x, b.y);
        *(unsigned*)(xr + 128 + k + 2) = packbf2(b.z, b.w);
        *(unsigned*)(xr + 256 + k)     = packbf2(c.x, c.y);
        *(unsigned*)(xr + 256 + k + 2) = packbf2(c.z, c.w);
        float s  = a.x+a.y+a.z+a.w + b.x+b.y+b.z+b.w + c.x+c.y+c.z+c.w;
        float ss = a.x*a.x+a.y*a.y+a.z*a.z+a.w*a.w
                 + b.x*b.x+b.y*b.y+b.z*b.z+b.w*b.w
                 + c.x*c.x+c.y*c.y+c.z*c.z+c.w*c.w;
        #pragma unroll
        for (int o = 16; o > 0; o >>= 1){
            s  += __shfl_xor_sync(0xFFFFFFFFu, s,  o);
            ss += __shfl_xor_sync(0xFFFFFFFFu, ss, o);
        }
        if (lane == 0){
            float mean = s * (1.0f / 384.0f);
            sMean[el] = mean;
            sRstd[el] = rsqrtf(ss * (1.0f / 384.0f) - mean * mean + 1e-5f);
        }
    }

    // pair barrier
    asm volatile("bar.sync %0, 64;" :: "r"((w & 3) + 1) : "memory");

    // ---- HMMA mainloop: warp tile 16(M) x 64(N); B via LDG.128 from L2 ----
    int mbase = (w & 3) * 16;
    int qb    = (w >> 2) * 2;
    int nbt   = qb * 4;
    float acc[8][4];
    #pragma unroll
    for (int j = 0; j < 8; j++)
        #pragma unroll
        for (int r = 0; r < 4; r++) acc[j][r] = 0.0f;

    uint32_t As_u = smem_u32(As);
    int arow = mbase + (lane & 15);
    int acol = (lane >> 4) * 8;
    const uint4* B0 = (const uint4*)g_Bf0 + qb * 32 + lane;
    const uint4* B1 = (const uint4*)g_Bf1 + qb * 32 + lane;

    #pragma unroll 3
    for (int s = 0; s < NKS; s++){
        uint4 u00 = __ldg(B0 + s * 128);
        uint4 u01 = __ldg(B0 + s * 128 + 32);
        uint4 u10 = __ldg(B1 + s * 128);
        uint4 u11 = __ldg(B1 + s * 128 + 32);
        uint32_t a0[4];
        uint32_t ad = As_u + (uint32_t)((arow * KP + s * 16 + acol) * 2);
        ldm_x4(a0, ad);
        mma16816(acc[0], a0, u00.x, u10.x);
        mma16816(acc[1], a0, u00.y, u10.y);
        mma16816(acc[2], a0, u00.z, u10.z);
        mma16816(acc[3], a0, u00.w, u10.w);
        mma16816(acc[4], a0, u01.x, u11.x);
        mma16816(acc[5], a0, u01.y, u11.y);
        mma16816(acc[6], a0, u01.z, u11.z);
        mma16816(acc[7], a0, u01.w, u11.w);
    }

    // ---- epilogue: LN fold + fast GELU + dot(w2) ----
    int half = w >> 2;
    {
        int r0 = mbase + gid;
        float mean0 = sMean[r0],     rstd0 = sRstd[r0];
        float mean1 = sMean[r0 + 8], rstd1 = sRstd[r0 + 8];
        float p0 = 0.0f, p1 = 0.0f;
        #pragma unroll
        for (int j = 0; j < 8; j++){
            int n0 = (nbt + j) * 8 + tig * 2;
            float2 uu = __ldg((const float2*)(g_U  + n0));
            float2 vb = __ldg((const float2*)(g_Vb + n0));
            float2 w2 = __ldg((const float2*)(bw2  + n0));
            float pre00 = rstd0 * (acc[j][0] - mean0 * uu.x) + vb.x;
            float pre01 = rstd0 * (acc[j][1] - mean0 * uu.y) + vb.y;
            float pre10 = rstd1 * (acc[j][2] - mean1 * uu.x) + vb.x;
            float pre11 = rstd1 * (acc[j][3] - mean1 * uu.y) + vb.y;
            p0 += gelu_t(pre00) * w2.x + gelu_t(pre01) * w2.y;
            p1 += gelu_t(pre10) * w2.x + gelu_t(pre11) * w2.y;
        }
        p0 += __shfl_xor_sync(0xFFFFFFFFu, p0, 1);
        p0 += __shfl_xor_sync(0xFFFFFFFFu, p0, 2);
        p1 += __shfl_xor_sync(0xFFFFFFFFu, p1, 1);
        p1 += __shfl_xor_sync(0xFFFFFFFFu, p1, 2);
        if (tig == 0){
            part[half * TM + r0]     = p0;
            part[half * TM + r0 + 8] = p1;
        }
    }
    __syncthreads();

    // final: logits + fused exp-sum (no max shift; |logit| small)
    if (w < 2){
        int el = w * 32 + lane;
        int e  = e0 + el;
        if (e < ET){
            float lg = part[el] + part[TM + el] + bb2[0];
            g_logits[e] = lg;
            atomicAdd(&g_tsum[tgt_s[el]], expf(lg));
        }
    }
}

// ---------------- pass3: log-softmax + per-graph scatter (log fused) ----------------
__global__ __launch_bounds__(256) void k_pass3(const int* __restrict__ eidx,
                                               const int* __restrict__ ebatch,
                                               const void* __restrict__ mask){
    int lane = threadIdx.x & 31;
    int e = (blockIdx.x * blockDim.x + threadIdx.x) * 4;
    if (e >= ET) return;
    int fl = g_mflag;
    int mode = (fl & 1) ? 2 : ((fl & 2) ? 0 : 1);

    int sel[4];
    if (mode == 0){
        uchar4 mv = *(const uchar4*)((const unsigned char*)mask + e);
        sel[0] = mv.x != 0; sel[1] = mv.y != 0; sel[2] = mv.z != 0; sel[3] = mv.w != 0;
    } else if (mode == 1){
        int4 mv = *(const int4*)((const int*)mask + e);
        sel[0] = mv.x != 0; sel[1] = mv.y != 0; sel[2] = mv.z != 0; sel[3] = mv.w != 0;
    } else {
        float4 mv = *(const float4*)((const float*)mask + e);
        sel[0] = mv.x != 0.f; sel[1] = mv.y != 0.f; sel[2] = mv.z != 0.f; sel[3] = mv.w != 0.f;
    }

    int4   tg = *(const int4*)(eidx + ET + e);
    int4   gb = *(const int4*)(ebatch + e);
    float4 sh = *(const float4*)(g_logits + e);

    float lp[4];
    lp[0] = sel[0] ? (sh.x - logf(g_tsum[tg.x])) : 0.0f;
    lp[1] = sel[1] ? (sh.y - logf(g_tsum[tg.y])) : 0.0f;
    lp[2] = sel[2] ? (sh.z - logf(g_tsum[tg.z])) : 0.0f;
    lp[3] = sel[3] ? (sh.w - logf(g_tsum[tg.w])) : 0.0f;
    int gbs[4] = {gb.x, gb.y, gb.z, gb.w};

    float v = 0.0f; int c = 0;
    int key = gbs[0];
    #pragma unroll
    for (int j = 0; j < 4; j++){
        if (gbs[j] == key){ v += lp[j]; c += sel[j]; }
        else if (sel[j]){
            atomicAdd(&g_logpb[gbs[j]], lp[j]);
            atomicAdd(&g_selcnt[gbs[j]], 1);
        }
    }

    #pragma unroll
    for (int off = 1; off < 32; off <<= 1){
        float ov = __shfl_down_sync(0xFFFFFFFFu, v, off);
        int   oc = __shfl_down_sync(0xFFFFFFFFu, c, off);
        int   ok = __shfl_down_sync(0xFFFFFFFFu, key, off);
        if (lane + off < 32 && ok == key){ v += ov; c += oc; }
    }
    int prevk = __shfl_up_sync(0xFFFFFFFFu, key, 1);
    bool leader = (lane == 0) || (prevk != key);
    if (leader && c > 0){
        atomicAdd(&g_logpb[key], v);
        atomicAdd(&g_selcnt[key], c);
    }
}

// ---------------- final ----------------
__global__ __launch_bounds__(1024) void k_final(float* __restrict__ out){
    __shared__ float rs[32];
    __shared__ int   ri[32];
    int t = threadIdx.x;
    float lp = g_logpb[t];
    int   c  = g_selcnt[t];
    float v = (c > 0) ? -lp : 0.0f;
    int   h = (c > 0) ? 1 : 0;
    #pragma unroll
    for (int o = 16; o > 0; o >>= 1){
        v += __shfl_xor_sync(0xFFFFFFFFu, v, o);
        h += __shfl_xor_sync(0xFFFFFFFFu, h, o);
    }
    if ((t & 31) == 0){ rs[t >> 5] = v; ri[t >> 5] = h; }
    __syncthreads();
    if (t < 32){
        float v2 = rs[t]; int h2 = ri[t];
        #pragma unroll
        for (int o = 16; o > 0; o >>= 1){
            v2 += __shfl_xor_sync(0xFFFFFFFFu, v2, o);
            h2 += __shfl_xor_sync(0xFFFFFFFFu, h2, o);
        }
        if (t == 0){ rs[0] = v2; ri[0] = h2; }
    }
    __syncthreads();
    float pbn = rs[0] / fmaxf((float)ri[0], 1.0f);
    out[t * 3 + 1] = lp;
    out[t * 3 + 2] = pbn;
}

// ---------------- launch ----------------
extern "C" void kernel_launch(void* const* d_in, const int* in_sizes, int n_in,
                              void* d_out, int out_size)
{
    int iN, iQ, iE, iLN1G, iLN1B, iZW1, iZB1, iZW2, iZB2,
        iCW1, iCB1, iCW2, iCB2, iBLG, iBLB, iBW1, iBB1, iBW2, iBB2,
        iLOC, iPTR, iEB, iMASK, iEIDX;
    if (in_sizes[3] == 4096){
        iN=0; iQ=1; iE=2; iLOC=3; iPTR=4; iEB=5; iMASK=6; iEIDX=7;
        iLN1G=8; iLN1B=9; iZW1=10; iZB1=11; iZW2=12; iZB2=13;
        iCW1=14; iCB1=15; iCW2=16; iCB2=17;
        iBLG=18; iBLB=19; iBW1=20; iBB1=21; iBW2=22; iBB2=23;
    } else {
        iN=0; iQ=1; iE=2;
        iLN1G=3; iLN1B=4; iZW1=5; iZB1=6; iZW2=7; iZB2=8;
        iCW1=9; iCB1=10; iCW2=11; iCB2=12;
        iBLG=13; iBLB=14; iBW1=15; iBB1=16; iBW2=17; iBB2=18;
        iLOC=19; iPTR=20; iEB=21; iMASK=22; iEIDX=23;
    }

    const float* node = (const float*)d_in[iN];
    const float* ques = (const float*)d_in[iQ];
    const float* etok = (const float*)d_in[iE];
    const float* ln1g = (const float*)d_in[iLN1G];
    const float* ln1b = (const float*)d_in[iLN1B];
    const float* zw1  = (const float*)d_in[iZW1];
    const float* zb1  = (const float*)d_in[iZB1];
    const float* zw2  = (const float*)d_in[iZW2];
    const float* zb2  = (const float*)d_in[iZB2];
    const float* cw1  = (const float*)d_in[iCW1];
    const float* cb1  = (const float*)d_in[iCB1];
    const float* cw2  = (const float*)d_in[iCW2];
    const float* cb2  = (const float*)d_in[iCB2];
    const float* blng = (const float*)d_in[iBLG];
    const float* blnb = (const float*)d_in[iBLB];
    const float* bw1  = (const float*)d_in[iBW1];
    const float* bb1  = (const float*)d_in[iBB1];
    const float* bw2  = (const float*)d_in[iBW2];
    const float* bb2  = (const float*)d_in[iBB2];
    const int* locals = (const int*)d_in[iLOC];
    const int* ptr    = (const int*)d_in[iPTR];
    const int* ebatch = (const int*)d_in[iEB];
    const void* mask  = (const void*)d_in[iMASK];
    const int* eidx   = (const int*)d_in[iEIDX];
    float* out = (float*)d_out;

    cudaFuncSetAttribute(k_main, cudaFuncAttributeMaxDynamicSharedMemorySize, MAIN_SMEM);

    k_prep<<<(NN + 255) / 256, 256>>>((const unsigned*)mask, bw1, blng, blnb, bb1);
    k_main<<<NG + EDGE_BLKS, 256, MAIN_SMEM>>>(node, ques, etok,
                                               bw2, bb2, ebatch, eidx,
                                               ln1g, ln1b, zw1, zb1, zw2, zb2,
                                               cw1, cb1, cw2, cb2, locals, ptr, out);
    k_pass3<<<(ET / 4 + 255) / 256, 256>>>(eidx, ebatch, mask);
    k_final<<<1, 1024>>>(out);
}